// round 9
// baseline (speedup 1.0000x reference)
#include <cuda_runtime.h>

#define NQ 2048
#define NB 8192
#define DIM 32
#define QT 16               // queries per block
#define THREADS 128
#define JR 2                // j's per thread
#define JBLK (THREADS * JR) // 256 j per block (SMEM-resident tile)
#define NJB (NB / JBLK)     // 32 j-splits
#define NWARP (THREADS / 32)

// Cross-block partials, laid out [query][split] so pass2 reads are contiguous
__device__ float g_pk [NQ * NJB];
__device__ float g_pky[NQ * NJB];

typedef unsigned long long ull;

__device__ __forceinline__ ull pk2(float lo, float hi) {
    ull r; asm("mov.b64 %0, {%1, %2};" : "=l"(r) : "f"(lo), "f"(hi)); return r;
}
__device__ __forceinline__ void upk2(ull v, float& lo, float& hi) {
    asm("mov.b64 {%0, %1}, %2;" : "=f"(lo), "=f"(hi) : "l"(v));
}
// Packed f32x2 math (Blackwell; PTX-only)
__device__ __forceinline__ ull fma2(ull a, ull b, ull c) {
    ull d; asm("fma.rn.f32x2 %0, %1, %2, %3;" : "=l"(d) : "l"(a), "l"(b), "l"(c)); return d;
}
__device__ __forceinline__ ull mul2(ull a, ull b) {
    ull d; asm("mul.rn.f32x2 %0, %1, %2;" : "=l"(d) : "l"(a), "l"(b)); return d;
}
__device__ __forceinline__ float ex2_approx(float x) {
    float y; asm("ex2.approx.f32 %0, %1;" : "=f"(y) : "f"(x)); return y;
}
__device__ __forceinline__ float sqrt_approx(float x) {
    float y; asm("sqrt.approx.f32 %0, %1;" : "=f"(y) : "f"(x)); return y;
}

__global__ __launch_bounds__(THREADS, 3)
void relnw_pass1(const float* __restrict__ xb,
                 const float* __restrict__ yb,
                 const float* __restrict__ xq,
                 const float* __restrict__ r,
                 const float* __restrict__ sigma,
                 const float* __restrict__ rscale,
                 const float* __restrict__ w)
{
    __shared__ ull   s_a[DIM / 2][QT];      // queries, [c][i], packed f32x2 (2 KB)
    __shared__ ull   s_xb[DIM / 2][JBLK];   // xb tile, [c][j], w-scaled (32 KB)
    __shared__ float s_b2[JBLK];            // ||xb_j * w||^2
    __shared__ float s_q2[QT];
    __shared__ ull   s_w2[DIM / 2];
    __shared__ float s_rk[NWARP][QT];
    __shared__ float s_ry[NWARP][QT];

    const int tid = threadIdx.x;
    const int bq  = blockIdx.x % (NQ / QT);
    const int bj  = blockIdx.x / (NQ / QT);
    const int i0  = bq * QT;
    const int J0  = bj * JBLK;
    const int l0  = tid;                 // local j indices owned by this thread
    const int l1  = tid + THREADS;
    const int j0  = J0 + l0;
    const int j1  = J0 + l1;

    if (tid < DIM / 2)
        s_w2[tid] = pk2(w[2 * tid], w[2 * tid + 1]);

    // Stage query fragment: 256 slots, 2 per thread
    #pragma unroll
    for (int t = tid; t < QT * (DIM / 2); t += THREADS) {
        const int i = t >> 4;
        const int c = t & 15;
        float a = xq[(i0 + i) * DIM + 2 * c]     * w[2 * c];
        float b = xq[(i0 + i) * DIM + 2 * c + 1] * w[2 * c + 1];
        s_a[c][i] = pk2(a, b);
    }
    __syncthreads();   // s_w2 + s_a visible

    // ---- prefetch r tile (DRAM latency hides under staging + mainloop)
    float rv[QT][JR];
    #pragma unroll
    for (int i = 0; i < QT; i++) {
        rv[i][0] = __ldg(r + (size_t)(i0 + i) * NB + j0);
        rv[i][1] = __ldg(r + (size_t)(i0 + i) * NB + j1);
    }

    if (tid < QT) {
        float s = 0.f;
        #pragma unroll
        for (int c = 0; c < DIM / 2; c++) {
            float a, b; upk2(s_a[c][tid], a, b);
            s = fmaf(a, a, s); s = fmaf(b, b, s);
        }
        s_q2[tid] = s;
    }

    // ---- stage xb tile transposed + w-scaled; compute ||.||^2 per row
    #pragma unroll
    for (int jr = 0; jr < JR; jr++) {
        const int j  = (jr == 0) ? j0 : j1;
        const int lj = (jr == 0) ? l0 : l1;
        const ulonglong2* p = reinterpret_cast<const ulonglong2*>(xb + (size_t)j * DIM);
        ull row[DIM / 2];
        #pragma unroll
        for (int c = 0; c < DIM / 4; c++) {
            ulonglong2 t = p[c];
            row[2 * c] = t.x; row[2 * c + 1] = t.y;
        }
        ull a2 = 0ull;
        #pragma unroll
        for (int c = 0; c < DIM / 2; c++) {
            row[c] = mul2(row[c], s_w2[c]);
            a2 = fma2(row[c], row[c], a2);
            s_xb[c][lj] = row[c];           // lanes -> consecutive j: conflict-free
        }
        float lo, hi; upk2(a2, lo, hi);
        s_b2[lj] = lo + hi;
    }
    __syncthreads();

    // ---- mainloop: 16 k-steps x (16 bcast LDS + 2 LDS + 32 independent fma2)
    ull acc[QT][JR];
    #pragma unroll
    for (int i = 0; i < QT; i++) { acc[i][0] = 0ull; acc[i][1] = 0ull; }

    #pragma unroll
    for (int c = 0; c < DIM / 2; c++) {
        const ull xv0 = s_xb[c][l0];
        const ull xv1 = s_xb[c][l1];
        #pragma unroll
        for (int i = 0; i < QT; i++) {
            const ull af = s_a[c][i];       // warp-uniform broadcast
            acc[i][0] = fma2(af, xv0, acc[i][0]);
            acc[i][1] = fma2(af, xv1, acc[i][1]);
        }
    }

    const float LOG2E = 1.4426950408889634f;
    const float c1 = -LOG2E / sigma[0];
    const float c2 =  LOG2E * rscale[0];
    const float b20 = s_b2[l0];
    const float b21 = s_b2[l1];
    const float yj0 = yb[j0];
    const float yj1 = yb[j1];

    // ---- epilogue: finish dots, kernel-eval, accumulate
    float sk[QT], sky[QT];
    #pragma unroll
    for (int i = 0; i < QT; i++) { sk[i] = 0.f; sky[i] = 0.f; }

    #pragma unroll
    for (int i = 0; i < QT; i++) {
        const float qb2 = s_q2[i];
        {
            float lo, hi; upk2(acc[i][0], lo, hi);
            const float d2   = fmaf(-2.f, lo + hi, qb2 + b20);
            const float dist = sqrt_approx(fmaxf(d2, 0.f));
            const float kv   = ex2_approx(fmaf(dist, c1, rv[i][0] * c2));
            sk[i]  += kv;
            sky[i]  = fmaf(kv, yj0, sky[i]);
        }
        {
            float lo, hi; upk2(acc[i][1], lo, hi);
            const float d2   = fmaf(-2.f, lo + hi, qb2 + b21);
            const float dist = sqrt_approx(fmaxf(d2, 0.f));
            const float kv   = ex2_approx(fmaf(dist, c1, rv[i][1] * c2));
            sk[i]  += kv;
            sky[i]  = fmaf(kv, yj1, sky[i]);
        }
    }

    // ---- deterministic block reduction
    const int wid = tid >> 5, lane = tid & 31;
    #pragma unroll
    for (int i = 0; i < QT; i++) {
        float a = sk[i], b = sky[i];
        #pragma unroll
        for (int off = 16; off > 0; off >>= 1) {
            a += __shfl_down_sync(0xffffffffu, a, off);
            b += __shfl_down_sync(0xffffffffu, b, off);
        }
        if (lane == 0) { s_rk[wid][i] = a; s_ry[wid][i] = b; }
    }
    __syncthreads();

    if (tid < QT) {
        float a = 0.f, b = 0.f;
        #pragma unroll
        for (int ww = 0; ww < NWARP; ww++) { a += s_rk[ww][tid]; b += s_ry[ww][tid]; }
        g_pk [(size_t)(i0 + tid) * NJB + bj] = a;   // [q][split] layout
        g_pky[(size_t)(i0 + tid) * NJB + bj] = b;
    }
}

__global__ __launch_bounds__(THREADS)
void relnw_pass2(float* __restrict__ out)
{
    const int i = blockIdx.x * blockDim.x + threadIdx.x;
    if (i < NQ) {
        const float4* pa = reinterpret_cast<const float4*>(g_pk  + (size_t)i * NJB);
        const float4* pb = reinterpret_cast<const float4*>(g_pky + (size_t)i * NJB);
        float a = 0.f, b = 0.f;
        #pragma unroll
        for (int s = 0; s < NJB / 4; s++) {         // contiguous float4 reads
            float4 va = pa[s], vb = pb[s];
            a += va.x; a += va.y; a += va.z; a += va.w;
            b += vb.x; b += vb.y; b += vb.z; b += vb.w;
        }
        out[i] = b / (a + 1e-8f);
    }
}

extern "C" void kernel_launch(void* const* d_in, const int* in_sizes, int n_in,
                              void* d_out, int out_size)
{
    const float* xb     = (const float*)d_in[0];  // x_backgnd (8192,32)
    const float* yb     = (const float*)d_in[1];  // y_backgnd (8192,)
    const float* xq     = (const float*)d_in[2];  // x_query   (2048,32)
    const float* r      = (const float*)d_in[3];  // r         (2048,8192)
    const float* sigma  = (const float*)d_in[4];  // (1,)
    const float* rscale = (const float*)d_in[5];  // (1,)
    const float* w      = (const float*)d_in[6];  // (32,)
    float* out = (float*)d_out;

    relnw_pass1<<<(NQ / QT) * NJB, THREADS>>>(xb, yb, xq, r, sigma, rscale, w);
    relnw_pass2<<<NQ / THREADS, THREADS>>>(out);
}

// round 12
// speedup vs baseline: 1.4692x; 1.4692x over previous
#include <cuda_runtime.h>

#define NQ 2048
#define NB 8192
#define DIM 32
#define QT 16               // queries per block
#define QH 4                // query quarter (register live-range reduction)
#define THREADS 256
#define JR 2                // j's per thread (register-resident xb rows)
#define JB (THREADS * JR)   // 512 j per block
#define NJB (NB / JB)       // 16 j-splits
#define NWARP (THREADS / 32)
#define NBQ (NQ / QT)       // 128 query tiles

// Cross-block partials, [query][split] so the fold reads are contiguous
__device__ float g_pk [NQ * NJB];
__device__ float g_pky[NQ * NJB];
__device__ int   g_cnt[NBQ];          // zero-init; self-resetting (graph-replay safe)

typedef unsigned long long ull;

__device__ __forceinline__ ull pk2(float lo, float hi) {
    ull r; asm("mov.b64 %0, {%1, %2};" : "=l"(r) : "f"(lo), "f"(hi)); return r;
}
__device__ __forceinline__ void upk2(ull v, float& lo, float& hi) {
    asm("mov.b64 {%0, %1}, %2;" : "=f"(lo), "=f"(hi) : "l"(v));
}
// Packed f32x2 math (Blackwell; PTX-only)
__device__ __forceinline__ ull fma2(ull a, ull b, ull c) {
    ull d; asm("fma.rn.f32x2 %0, %1, %2, %3;" : "=l"(d) : "l"(a), "l"(b), "l"(c)); return d;
}
__device__ __forceinline__ ull mul2(ull a, ull b) {
    ull d; asm("mul.rn.f32x2 %0, %1, %2;" : "=l"(d) : "l"(a), "l"(b)); return d;
}
__device__ __forceinline__ float ex2_approx(float x) {
    float y; asm("ex2.approx.f32 %0, %1;" : "=f"(y) : "f"(x)); return y;
}
__device__ __forceinline__ float sqrt_approx(float x) {
    float y; asm("sqrt.approx.f32 %0, %1;" : "=f"(y) : "f"(x)); return y;
}

__global__ __launch_bounds__(THREADS, 2)
void relnw_fused(const float* __restrict__ xb,
                 const float* __restrict__ yb,
                 const float* __restrict__ xq,
                 const float* __restrict__ r,
                 const float* __restrict__ sigma,
                 const float* __restrict__ rscale,
                 const float* __restrict__ w,
                 float* __restrict__ out)
{
    __shared__ ull   s_a[DIM / 2][QT];   // w-scaled queries, [c][i], packed f32x2
    __shared__ float s_q2[QT];
    __shared__ ull   s_w2[DIM / 2];
    __shared__ float s_rk[NWARP][QT];
    __shared__ float s_ry[NWARP][QT];
    __shared__ int   s_last;

    const int tid = threadIdx.x;
    const int bq  = blockIdx.x & (NBQ - 1);
    const int bj  = blockIdx.x >> 7;          // NBQ == 128
    const int i0  = bq * QT;
    const int j0  = bj * JB + tid;            // this thread's two j's
    const int j1  = j0 + THREADS;

    if (tid < DIM / 2)
        s_w2[tid] = pk2(w[2 * tid], w[2 * tid + 1]);

    // Stage query fragment: 256 threads = 16 queries x 16 f32x2 slots
    {
        const int i = tid >> 4;
        const int c = tid & 15;
        float a = xq[(i0 + i) * DIM + 2 * c]     * w[2 * c];
        float b = xq[(i0 + i) * DIM + 2 * c + 1] * w[2 * c + 1];
        s_a[c][i] = pk2(a, b);
    }
    __syncthreads();

    if (tid < QT) {
        float s = 0.f;
        #pragma unroll
        for (int c = 0; c < DIM / 2; c++) {
            float a, b; upk2(s_a[c][tid], a, b);
            s = fmaf(a, a, s); s = fmaf(b, b, s);
        }
        s_q2[tid] = s;
    }

    // ---- load & w-scale this thread's two xb rows into registers
    ull   xv[JR][DIM / 2];
    float b2[JR];
    #pragma unroll
    for (int jr = 0; jr < JR; jr++) {
        const int j = (jr == 0) ? j0 : j1;
        const ulonglong2* p = reinterpret_cast<const ulonglong2*>(xb + (size_t)j * DIM);
        #pragma unroll
        for (int c = 0; c < DIM / 4; c++) {
            ulonglong2 t = p[c];
            xv[jr][2 * c] = t.x; xv[jr][2 * c + 1] = t.y;
        }
        ull a2 = 0ull;
        #pragma unroll
        for (int c = 0; c < DIM / 2; c++) {
            xv[jr][c] = mul2(xv[jr][c], s_w2[c]);
            a2 = fma2(xv[jr][c], xv[jr][c], a2);
        }
        float lo, hi; upk2(a2, lo, hi);
        b2[jr] = lo + hi;
    }
    __syncthreads();   // s_q2 ready

    const float LOG2E = 1.4426950408889634f;
    const float c1 = -LOG2E / sigma[0];
    const float c2 =  LOG2E * rscale[0];
    const float yj0 = yb[j0];
    const float yj1 = yb[j1];
    const int wid = tid >> 5, lane = tid & 31;

    // ---- prefetch r for quarter 0
    float rv[QH][JR];
    #pragma unroll
    for (int qi = 0; qi < QH; qi++) {
        rv[qi][0] = __ldg(r + (size_t)(i0 + qi) * NB + j0);
        rv[qi][1] = __ldg(r + (size_t)(i0 + qi) * NB + j1);
    }

    // ---- process 4 query-quarters; small acc/rv live sets keep regs <=128
    #pragma unroll
    for (int h = 0; h < QT / QH; h++) {
        const int ib = h * QH;

        // prefetch next quarter's r before the mainloop (latency hides under it)
        float rn[QH][JR];
        if (h < QT / QH - 1) {
            #pragma unroll
            for (int qi = 0; qi < QH; qi++) {
                rn[qi][0] = __ldg(r + (size_t)(i0 + ib + QH + qi) * NB + j0);
                rn[qi][1] = __ldg(r + (size_t)(i0 + ib + QH + qi) * NB + j1);
            }
        }

        // mainloop: 16 k-steps x (4 bcast LDS + 8 independent fma2)
        ull acc[QH][JR];
        #pragma unroll
        for (int qi = 0; qi < QH; qi++) { acc[qi][0] = 0ull; acc[qi][1] = 0ull; }

        #pragma unroll
        for (int c = 0; c < DIM / 2; c++) {
            #pragma unroll
            for (int qi = 0; qi < QH; qi++) {
                const ull af = s_a[c][ib + qi];     // warp-uniform broadcast
                acc[qi][0] = fma2(af, xv[0][c], acc[qi][0]);
                acc[qi][1] = fma2(af, xv[1][c], acc[qi][1]);
            }
        }

        // epilogue for this quarter
        #pragma unroll
        for (int qi = 0; qi < QH; qi++) {
            const float qb2 = s_q2[ib + qi];
            float sk, sky;
            {
                float lo, hi; upk2(acc[qi][0], lo, hi);
                const float d2   = fmaf(-2.f, lo + hi, qb2 + b2[0]);
                const float dist = sqrt_approx(fmaxf(d2, 0.f));
                const float kv   = ex2_approx(fmaf(dist, c1, rv[qi][0] * c2));
                sk  = kv;
                sky = kv * yj0;
            }
            {
                float lo, hi; upk2(acc[qi][1], lo, hi);
                const float d2   = fmaf(-2.f, lo + hi, qb2 + b2[1]);
                const float dist = sqrt_approx(fmaxf(d2, 0.f));
                const float kv   = ex2_approx(fmaf(dist, c1, rv[qi][1] * c2));
                sk  += kv;
                sky  = fmaf(kv, yj1, sky);
            }
            // deterministic warp reduction
            #pragma unroll
            for (int off = 16; off > 0; off >>= 1) {
                sk  += __shfl_down_sync(0xffffffffu, sk,  off);
                sky += __shfl_down_sync(0xffffffffu, sky, off);
            }
            if (lane == 0) { s_rk[wid][ib + qi] = sk; s_ry[wid][ib + qi] = sky; }
        }

        // rotate r double-buffer
        if (h < QT / QH - 1) {
            #pragma unroll
            for (int qi = 0; qi < QH; qi++) { rv[qi][0] = rn[qi][0]; rv[qi][1] = rn[qi][1]; }
        }
    }

    __syncthreads();

    // ---- per-block partials (fixed-order SMEM fold)
    if (tid < QT) {
        float a = 0.f, b = 0.f;
        #pragma unroll
        for (int ww = 0; ww < NWARP; ww++) { a += s_rk[ww][tid]; b += s_ry[ww][tid]; }
        g_pk [(size_t)(i0 + tid) * NJB + bj] = a;
        g_pky[(size_t)(i0 + tid) * NJB + bj] = b;
    }
    __syncthreads();

    // ---- last block for this query tile folds the splits (saves a 2nd launch)
    if (tid == 0) {
        __threadfence();
        int old = atomicAdd(&g_cnt[bq], 1);
        s_last = (old == NJB - 1);
        if (s_last) atomicSub(&g_cnt[bq], NJB);   // self-reset for graph replay
    }
    __syncthreads();

    if (s_last && tid < QT) {
        const float* pa = g_pk  + (size_t)(i0 + tid) * NJB;
        const float* pb = g_pky + (size_t)(i0 + tid) * NJB;
        float a = 0.f, b = 0.f;
        #pragma unroll
        for (int s = 0; s < NJB; s++) {           // fixed order: deterministic
            a += __ldcg(pa + s);                  // L2 reads: dodge stale L1
            b += __ldcg(pb + s);
        }
        out[i0 + tid] = b / (a + 1e-8f);
    }
}

extern "C" void kernel_launch(void* const* d_in, const int* in_sizes, int n_in,
                              void* d_out, int out_size)
{
    const float* xb     = (const float*)d_in[0];  // x_backgnd (8192,32)
    const float* yb     = (const float*)d_in[1];  // y_backgnd (8192,)
    const float* xq     = (const float*)d_in[2];  // x_query   (2048,32)
    const float* r      = (const float*)d_in[3];  // r         (2048,8192)
    const float* sigma  = (const float*)d_in[4];  // (1,)
    const float* rscale = (const float*)d_in[5];  // (1,)
    const float* w      = (const float*)d_in[6];  // (32,)
    float* out = (float*)d_out;

    relnw_fused<<<NBQ * NJB, THREADS>>>(xb, yb, xq, r, sigma, rscale, w, out);
}

// round 13
// speedup vs baseline: 1.5420x; 1.0496x over previous
#include <cuda_runtime.h>

#define NQ 2048
#define NB 8192
#define DIM 32
#define QT 16               // queries per block
#define QH 4                // query quarter (acc live-range reduction)
#define THREADS 256
#define JR 2                // adjacent j's per thread
#define JB (THREADS * JR)   // 512 j per block
#define NJB (NB / JB)       // 16 j-splits
#define NWARP (THREADS / 32)
#define NBQ (NQ / QT)       // 128 query tiles

// Cross-block partials, [query][split]; counter self-resets (graph-replay safe)
__device__ float g_pk [NQ * NJB];
__device__ float g_pky[NQ * NJB];
__device__ int   g_cnt[NBQ];

typedef unsigned long long ull;

__device__ __forceinline__ ull pk2(float lo, float hi) {
    ull r; asm("mov.b64 %0, {%1, %2};" : "=l"(r) : "f"(lo), "f"(hi)); return r;
}
__device__ __forceinline__ void upk2(ull v, float& lo, float& hi) {
    asm("mov.b64 {%0, %1}, %2;" : "=f"(lo), "=f"(hi) : "l"(v));
}
// Packed f32x2 math (Blackwell; PTX-only)
__device__ __forceinline__ ull fma2(ull a, ull b, ull c) {
    ull d; asm("fma.rn.f32x2 %0, %1, %2, %3;" : "=l"(d) : "l"(a), "l"(b), "l"(c)); return d;
}
__device__ __forceinline__ ull mul2(ull a, ull b) {
    ull d; asm("mul.rn.f32x2 %0, %1, %2;" : "=l"(d) : "l"(a), "l"(b)); return d;
}
__device__ __forceinline__ float ex2_approx(float x) {
    float y; asm("ex2.approx.f32 %0, %1;" : "=f"(y) : "f"(x)); return y;
}
__device__ __forceinline__ float sqrt_approx(float x) {
    float y; asm("sqrt.approx.f32 %0, %1;" : "=f"(y) : "f"(x)); return y;
}

__global__ __launch_bounds__(THREADS, 2)
void relnw_fused(const float* __restrict__ xb,
                 const float* __restrict__ yb,
                 const float* __restrict__ xq,
                 const float* __restrict__ r,
                 const float* __restrict__ sigma,
                 const float* __restrict__ rscale,
                 const float* __restrict__ w,
                 float* __restrict__ out)
{
    // s_a laid out [query][c] so one LDS.128 broadcast feeds TWO k-steps
    __shared__ ull   s_a[QT][DIM / 2];
    __shared__ float s_q2[QT];
    __shared__ ull   s_w2[DIM / 2];
    __shared__ float s_rk[NWARP][QT];
    __shared__ float s_ry[NWARP][QT];
    __shared__ int   s_last;

    const int tid = threadIdx.x;
    const int bq  = blockIdx.x & (NBQ - 1);
    const int bj  = blockIdx.x >> 7;            // NBQ == 128
    const int i0  = bq * QT;
    const int j0  = bj * JB + 2 * tid;          // ADJACENT j pair per thread
    const int j1  = j0 + 1;

    if (tid < DIM / 2)
        s_w2[tid] = pk2(w[2 * tid], w[2 * tid + 1]);

    // Stage query fragment: 256 threads = 16 queries x 16 f32x2 slots
    {
        const int i = tid >> 4;
        const int c = tid & 15;
        float a = xq[(i0 + i) * DIM + 2 * c]     * w[2 * c];
        float b = xq[(i0 + i) * DIM + 2 * c + 1] * w[2 * c + 1];
        s_a[i][c] = pk2(a, b);
    }
    __syncthreads();

    if (tid < QT) {
        float s = 0.f;
        #pragma unroll
        for (int c = 0; c < DIM / 2; c++) {
            float a, b; upk2(s_a[tid][c], a, b);
            s = fmaf(a, a, s); s = fmaf(b, b, s);
        }
        s_q2[tid] = s;
    }

    // ---- FULL r prefetch: 16 float2 loads, MLP=16/thread, one exposure for
    //      the whole block (this is what made Round 4 fast)
    float2 rv[QT];
    #pragma unroll
    for (int i = 0; i < QT; i++)
        rv[i] = __ldg(reinterpret_cast<const float2*>(r + (size_t)(i0 + i) * NB + j0));

    const float2 yj = __ldg(reinterpret_cast<const float2*>(yb + j0));

    // ---- load & w-scale this thread's two (adjacent) xb rows into registers
    ull   xv[JR][DIM / 2];
    float b2[JR];
    #pragma unroll
    for (int jr = 0; jr < JR; jr++) {
        const int j = j0 + jr;
        const ulonglong2* p = reinterpret_cast<const ulonglong2*>(xb + (size_t)j * DIM);
        #pragma unroll
        for (int c = 0; c < DIM / 4; c++) {
            ulonglong2 t = p[c];
            xv[jr][2 * c] = t.x; xv[jr][2 * c + 1] = t.y;
        }
        ull a2 = 0ull;
        #pragma unroll
        for (int c = 0; c < DIM / 2; c++) {
            xv[jr][c] = mul2(xv[jr][c], s_w2[c]);
            a2 = fma2(xv[jr][c], xv[jr][c], a2);
        }
        float lo, hi; upk2(a2, lo, hi);
        b2[jr] = lo + hi;
    }
    __syncthreads();   // s_q2 ready

    const float LOG2E = 1.4426950408889634f;
    const float c1 = -LOG2E / sigma[0];
    const float c2 =  LOG2E * rscale[0];
    const int wid = tid >> 5, lane = tid & 31;

    // ---- 4 query-quarters: small acc live set, LDS.128 broadcasts
    #pragma unroll
    for (int h = 0; h < QT / QH; h++) {
        const int ib = h * QH;

        ull acc[QH][JR];
        #pragma unroll
        for (int qi = 0; qi < QH; qi++) { acc[qi][0] = 0ull; acc[qi][1] = 0ull; }

        // 8 outer steps; each LDS.128 broadcast feeds 2 k-steps (4 fma2/query)
        #pragma unroll
        for (int c2i = 0; c2i < DIM / 4; c2i++) {
            #pragma unroll
            for (int qi = 0; qi < QH; qi++) {
                const ulonglong2 af2 =
                    *reinterpret_cast<const ulonglong2*>(&s_a[ib + qi][2 * c2i]);
                acc[qi][0] = fma2(af2.x, xv[0][2 * c2i],     acc[qi][0]);
                acc[qi][1] = fma2(af2.x, xv[1][2 * c2i],     acc[qi][1]);
                acc[qi][0] = fma2(af2.y, xv[0][2 * c2i + 1], acc[qi][0]);
                acc[qi][1] = fma2(af2.y, xv[1][2 * c2i + 1], acc[qi][1]);
            }
        }

        // epilogue for this quarter
        #pragma unroll
        for (int qi = 0; qi < QH; qi++) {
            const float qb2 = s_q2[ib + qi];
            float sk, sky;
            {
                float lo, hi; upk2(acc[qi][0], lo, hi);
                const float d2   = fmaf(-2.f, lo + hi, qb2 + b2[0]);
                const float dist = sqrt_approx(fmaxf(d2, 0.f));
                const float kv   = ex2_approx(fmaf(dist, c1, rv[ib + qi].x * c2));
                sk  = kv;
                sky = kv * yj.x;
            }
            {
                float lo, hi; upk2(acc[qi][1], lo, hi);
                const float d2   = fmaf(-2.f, lo + hi, qb2 + b2[1]);
                const float dist = sqrt_approx(fmaxf(d2, 0.f));
                const float kv   = ex2_approx(fmaf(dist, c1, rv[ib + qi].y * c2));
                sk  += kv;
                sky  = fmaf(kv, yj.y, sky);
            }
            // deterministic warp reduction
            #pragma unroll
            for (int off = 16; off > 0; off >>= 1) {
                sk  += __shfl_down_sync(0xffffffffu, sk,  off);
                sky += __shfl_down_sync(0xffffffffu, sky, off);
            }
            if (lane == 0) { s_rk[wid][ib + qi] = sk; s_ry[wid][ib + qi] = sky; }
        }
    }

    __syncthreads();

    // ---- per-block partials (fixed-order fold: deterministic)
    if (tid < QT) {
        float a = 0.f, b = 0.f;
        #pragma unroll
        for (int ww = 0; ww < NWARP; ww++) { a += s_rk[ww][tid]; b += s_ry[ww][tid]; }
        g_pk [(size_t)(i0 + tid) * NJB + bj] = a;
        g_pky[(size_t)(i0 + tid) * NJB + bj] = b;
    }
    __syncthreads();

    // ---- last block for this query tile folds the splits
    if (tid == 0) {
        __threadfence();
        int old = atomicAdd(&g_cnt[bq], 1);
        s_last = (old == NJB - 1);
        if (s_last) atomicSub(&g_cnt[bq], NJB);   // self-reset for graph replay
    }
    __syncthreads();

    if (s_last && tid < QT) {
        const float* pa = g_pk  + (size_t)(i0 + tid) * NJB;
        const float* pb = g_pky + (size_t)(i0 + tid) * NJB;
        float a = 0.f, b = 0.f;
        #pragma unroll
        for (int s = 0; s < NJB; s++) {           // fixed order: deterministic
            a += __ldcg(pa + s);                  // L2 reads: dodge stale L1
            b += __ldcg(pb + s);
        }
        out[i0 + tid] = b / (a + 1e-8f);
    }
}

extern "C" void kernel_launch(void* const* d_in, const int* in_sizes, int n_in,
                              void* d_out, int out_size)
{
    const float* xb     = (const float*)d_in[0];  // x_backgnd (8192,32)
    const float* yb     = (const float*)d_in[1];  // y_backgnd (8192,)
    const float* xq     = (const float*)d_in[2];  // x_query   (2048,32)
    const float* r      = (const float*)d_in[3];  // r         (2048,8192)
    const float* sigma  = (const float*)d_in[4];  // (1,)
    const float* rscale = (const float*)d_in[5];  // (1,)
    const float* w      = (const float*)d_in[6];  // (32,)
    float* out = (float*)d_out;

    relnw_fused<<<NBQ * NJB, THREADS>>>(xb, yb, xq, r, sigma, rscale, w, out);
}

// round 17
// speedup vs baseline: 2.0045x; 1.2999x over previous
#include <cuda_runtime.h>

#define NQ 2048
#define NB 8192
#define DIM 32
#define QT 16               // queries per block
#define QH 4                // query quarter (acc live-range reduction)
#define THREADS 256
#define JB 512              // j per block
#define HB 256              // rows per staging half
#define NJB (NB / JB)       // 16 j-splits
#define NWARP (THREADS / 32)
#define NBQ (NQ / QT)       // 128 query tiles
#define RSTRIDE 36          // padded SMEM row stride in words (144B)

// Cross-block partials, [query][split]; counter self-resets (graph-replay safe)
__device__ float g_pk [NQ * NJB];
__device__ float g_pky[NQ * NJB];
__device__ int   g_cnt[NBQ];

typedef unsigned long long ull;

__device__ __forceinline__ ull pk2(float lo, float hi) {
    ull r; asm("mov.b64 %0, {%1, %2};" : "=l"(r) : "f"(lo), "f"(hi)); return r;
}
__device__ __forceinline__ void upk2(ull v, float& lo, float& hi) {
    asm("mov.b64 {%0, %1}, %2;" : "=f"(lo), "=f"(hi) : "l"(v));
}
// Packed f32x2 math (Blackwell; PTX-only)
__device__ __forceinline__ ull fma2(ull a, ull b, ull c) {
    ull d; asm("fma.rn.f32x2 %0, %1, %2, %3;" : "=l"(d) : "l"(a), "l"(b), "l"(c)); return d;
}
__device__ __forceinline__ float ex2_approx(float x) {
    float y; asm("ex2.approx.f32 %0, %1;" : "=f"(y) : "f"(x)); return y;
}
__device__ __forceinline__ float sqrt_approx(float x) {
    float y; asm("sqrt.approx.f32 %0, %1;" : "=f"(y) : "f"(x)); return y;
}

__global__ __launch_bounds__(THREADS, 2)
void relnw_fused(const float* __restrict__ xb,
                 const float* __restrict__ yb,
                 const float* __restrict__ xq,
                 const float* __restrict__ r,
                 const float* __restrict__ sigma,
                 const float* __restrict__ rscale,
                 const float* __restrict__ w,
                 float* __restrict__ out)
{
    __shared__ float s_xb[HB * RSTRIDE];   // staging half-tile, padded rows (36.9KB)
    __shared__ ull   s_a[QT][DIM / 2];     // w-scaled queries [query][c] (LDS.128 bcast)
    __shared__ float s_q2[QT];
    __shared__ float s_rk[NWARP][QT];
    __shared__ float s_ry[NWARP][QT];
    __shared__ int   s_last;

    const int tid = threadIdx.x;
    const int bq  = blockIdx.x & (NBQ - 1);
    const int bj  = blockIdx.x >> 7;            // NBQ == 128
    const int i0  = bq * QT;
    const int J0  = bj * JB;
    const int j0  = J0 + tid;                   // this thread's j pair
    const int j1  = j0 + HB;

    // Stage query fragment: 256 threads = 16 queries x 16 f32x2 slots
    {
        const int i = tid >> 4;
        const int c = tid & 15;
        float a = xq[(i0 + i) * DIM + 2 * c]     * w[2 * c];
        float b = xq[(i0 + i) * DIM + 2 * c + 1] * w[2 * c + 1];
        s_a[i][c] = pk2(a, b);
    }

    // ---- r prefetch: fully coalesced LDG.32 (1 line/warp/instr), MLP=32.
    //      DRAM latency hides under the xb staging below.
    float rv0[QT], rv1[QT];
    #pragma unroll
    for (int i = 0; i < QT; i++)
        rv0[i] = __ldg(r + (size_t)(i0 + i) * NB + j0);
    #pragma unroll
    for (int i = 0; i < QT; i++)
        rv1[i] = __ldg(r + (size_t)(i0 + i) * NB + j1);
    const float yj0 = yb[j0];
    const float yj1 = yb[j1];

    __syncthreads();   // s_a visible

    if (tid < QT) {
        float s = 0.f;
        #pragma unroll
        for (int c = 0; c < DIM / 2; c++) {
            float a, b; upk2(s_a[tid][c], a, b);
            s = fmaf(a, a, s); s = fmaf(b, b, s);
        }
        s_q2[tid] = s;
    }

    // ---- xb staging: two halves through SMEM.
    //      LDG coalesced (1 wf/instr), STS/LDS conflict-free via 144B row pad.
    const int chunk = tid & 7;                          // this thread's 16B chunk
    const float4 w4 = *reinterpret_cast<const float4*>(w + 4 * chunk);

    ull   xv[2][DIM / 2];
    float b2[2];
    #pragma unroll
    for (int p = 0; p < 2; p++) {
        const int Jp = J0 + p * HB;
        __syncthreads();                                // buffer safe to (re)write
        #pragma unroll
        for (int k = 0; k < 8; k++) {
            const int row = k * 32 + (tid >> 3);        // 0..255
            float4 v = __ldg(reinterpret_cast<const float4*>(
                                 xb + (size_t)(Jp + row) * DIM) + chunk);
            v.x *= w4.x; v.y *= w4.y; v.z *= w4.z; v.w *= w4.w;
            *reinterpret_cast<float4*>(&s_xb[row * RSTRIDE + chunk * 4]) = v;
        }
        __syncthreads();                                // half staged
        ull a2 = 0ull;
        #pragma unroll
        for (int c = 0; c < DIM / 4; c++) {             // conflict-free readback
            float4 v = *reinterpret_cast<const float4*>(&s_xb[tid * RSTRIDE + c * 4]);
            xv[p][2 * c]     = pk2(v.x, v.y);
            xv[p][2 * c + 1] = pk2(v.z, v.w);
            a2 = fma2(xv[p][2 * c],     xv[p][2 * c],     a2);
            a2 = fma2(xv[p][2 * c + 1], xv[p][2 * c + 1], a2);
        }
        float lo, hi; upk2(a2, lo, hi);
        b2[p] = lo + hi;
    }
    __syncthreads();   // s_q2 + staging complete

    const float LOG2E = 1.4426950408889634f;
    const float c1 = -LOG2E / sigma[0];
    const float c2 =  LOG2E * rscale[0];
    const int wid = tid >> 5, lane = tid & 31;

    // ---- 4 query-quarters: LDS.128 broadcast feeds 2 k-steps x 2 j
    #pragma unroll
    for (int h = 0; h < QT / QH; h++) {
        const int ib = h * QH;

        ull acc[QH][2];
        #pragma unroll
        for (int qi = 0; qi < QH; qi++) { acc[qi][0] = 0ull; acc[qi][1] = 0ull; }

        #pragma unroll
        for (int c2i = 0; c2i < DIM / 4; c2i++) {
            #pragma unroll
            for (int qi = 0; qi < QH; qi++) {
                const ulonglong2 af2 =
                    *reinterpret_cast<const ulonglong2*>(&s_a[ib + qi][2 * c2i]);
                acc[qi][0] = fma2(af2.x, xv[0][2 * c2i],     acc[qi][0]);
                acc[qi][1] = fma2(af2.x, xv[1][2 * c2i],     acc[qi][1]);
                acc[qi][0] = fma2(af2.y, xv[0][2 * c2i + 1], acc[qi][0]);
                acc[qi][1] = fma2(af2.y, xv[1][2 * c2i + 1], acc[qi][1]);
            }
        }

        // epilogue for this quarter
        #pragma unroll
        for (int qi = 0; qi < QH; qi++) {
            const float qb2 = s_q2[ib + qi];
            float sk, sky;
            {
                float lo, hi; upk2(acc[qi][0], lo, hi);
                const float d2   = fmaf(-2.f, lo + hi, qb2 + b2[0]);
                const float dist = sqrt_approx(fmaxf(d2, 0.f));
                const float kv   = ex2_approx(fmaf(dist, c1, rv0[ib + qi] * c2));
                sk  = kv;
                sky = kv * yj0;
            }
            {
                float lo, hi; upk2(acc[qi][1], lo, hi);
                const float d2   = fmaf(-2.f, lo + hi, qb2 + b2[1]);
                const float dist = sqrt_approx(fmaxf(d2, 0.f));
                const float kv   = ex2_approx(fmaf(dist, c1, rv1[ib + qi] * c2));
                sk  += kv;
                sky  = fmaf(kv, yj1, sky);
            }
            // deterministic warp reduction
            #pragma unroll
            for (int off = 16; off > 0; off >>= 1) {
                sk  += __shfl_down_sync(0xffffffffu, sk,  off);
                sky += __shfl_down_sync(0xffffffffu, sky, off);
            }
            if (lane == 0) { s_rk[wid][ib + qi] = sk; s_ry[wid][ib + qi] = sky; }
        }
    }

    __syncthreads();

    // ---- per-block partials (fixed-order fold: deterministic)
    if (tid < QT) {
        float a = 0.f, b = 0.f;
        #pragma unroll
        for (int ww = 0; ww < NWARP; ww++) { a += s_rk[ww][tid]; b += s_ry[ww][tid]; }
        g_pk [(size_t)(i0 + tid) * NJB + bj] = a;
        g_pky[(size_t)(i0 + tid) * NJB + bj] = b;
    }
    __syncthreads();

    // ---- last block for this query tile folds the splits
    if (tid == 0) {
        __threadfence();
        int old = atomicAdd(&g_cnt[bq], 1);
        s_last = (old == NJB - 1);
        if (s_last) atomicSub(&g_cnt[bq], NJB);   // self-reset for graph replay
    }
    __syncthreads();

    if (s_last && tid < QT) {
        const float* pa = g_pk  + (size_t)(i0 + tid) * NJB;
        const float* pb = g_pky + (size_t)(i0 + tid) * NJB;
        float a = 0.f, b = 0.f;
        #pragma unroll
        for (int s = 0; s < NJB; s++) {           // fixed order: deterministic
            a += __ldcg(pa + s);                  // L2 reads: dodge stale L1
            b += __ldcg(pb + s);
        }
        out[i0 + tid] = b / (a + 1e-8f);
    }
}

extern "C" void kernel_launch(void* const* d_in, const int* in_sizes, int n_in,
                              void* d_out, int out_size)
{
    const float* xb     = (const float*)d_in[0];  // x_backgnd (8192,32)
    const float* yb     = (const float*)d_in[1];  // y_backgnd (8192,)
    const float* xq     = (const float*)d_in[2];  // x_query   (2048,32)
    const float* r      = (const float*)d_in[3];  // r         (2048,8192)
    const float* sigma  = (const float*)d_in[4];  // (1,)
    const float* rscale = (const float*)d_in[5];  // (1,)
    const float* w      = (const float*)d_in[6];  // (32,)
    float* out = (float*)d_out;

    relnw_fused<<<NBQ * NJB, THREADS>>>(xb, yb, xq, r, sigma, rscale, w, out);
}